// round 1
// baseline (speedup 1.0000x reference)
#include <cuda_runtime.h>

// Problem constants
#define BB 2
#define SS 2048
#define EE 1024
#define HH 16
#define DD 64
// M = BB*SS = 4096, QKV N = 3072, out N = 1024, K = 1024

// Scratch (device globals: allocation-free rule)
__device__ float g_qkv[3 * BB * HH * SS * DD];   // [which][b][h][s][d]
__device__ float g_ctx[BB * SS * EE];            // [b][s][h*64+d]

// ---------------------------------------------------------------------------
// SGEMM (NT): C[M,N] = A[M,K] @ W[N,K]^T + bias[N]
// MODE 0: A = g_ctx (internal), plain row-major output to Cout
// MODE 1: A = x (param), scatter output into g_qkv [which][b][h][s][d]
// BM=128, BN=128, BK=8, 256 threads, 8x8 per thread.
// ---------------------------------------------------------------------------
template <int MODE, int N, int K>
__global__ __launch_bounds__(256) void sgemm_nt(const float* __restrict__ A,
                                                const float* __restrict__ W,
                                                const float* __restrict__ bias,
                                                float* __restrict__ Cout) {
    __shared__ float As[8][132];
    __shared__ float Bs[8][132];

    const float* Ap = (MODE == 0) ? (const float*)g_ctx : A;

    int tid = threadIdx.x;
    int m0 = blockIdx.y * 128;
    int n0 = blockIdx.x * 128;
    int tx = tid & 15;        // 0..15 -> n
    int ty = tid >> 4;        // 0..15 -> m
    int lr = tid >> 1;        // 0..127 tile row for loads
    int lk = (tid & 1) * 4;   // 0 or 4

    float acc[8][8];
#pragma unroll
    for (int i = 0; i < 8; i++)
#pragma unroll
        for (int j = 0; j < 8; j++) acc[i][j] = 0.0f;

    for (int k0 = 0; k0 < K; k0 += 8) {
        float4 a4 = *(const float4*)(Ap + (m0 + lr) * K + k0 + lk);
        float4 b4 = *(const float4*)(W + (n0 + lr) * K + k0 + lk);
        __syncthreads();
        As[lk + 0][lr] = a4.x; As[lk + 1][lr] = a4.y;
        As[lk + 2][lr] = a4.z; As[lk + 3][lr] = a4.w;
        Bs[lk + 0][lr] = b4.x; Bs[lk + 1][lr] = b4.y;
        Bs[lk + 2][lr] = b4.z; Bs[lk + 3][lr] = b4.w;
        __syncthreads();
#pragma unroll
        for (int kk = 0; kk < 8; kk++) {
            float a[8], bb[8];
            *(float4*)&a[0]  = *(const float4*)&As[kk][ty * 8];
            *(float4*)&a[4]  = *(const float4*)&As[kk][ty * 8 + 4];
            *(float4*)&bb[0] = *(const float4*)&Bs[kk][tx * 8];
            *(float4*)&bb[4] = *(const float4*)&Bs[kk][tx * 8 + 4];
#pragma unroll
            for (int i = 0; i < 8; i++)
#pragma unroll
                for (int j = 0; j < 8; j++) acc[i][j] += a[i] * bb[j];
        }
    }

    if (MODE == 0) {
#pragma unroll
        for (int i = 0; i < 8; i++) {
            int m = m0 + ty * 8 + i;
#pragma unroll
            for (int j = 0; j < 8; j++) {
                int n = n0 + tx * 8 + j;
                Cout[m * N + n] = acc[i][j] + bias[n];
            }
        }
    } else {
        // scatter into q/k/v: n -> (which, h, d)
        int n_base = n0 + tx * 8;          // 8 consecutive n share which,h
        int which = n_base >> 10;
        int e = n_base & 1023;
        int h = e >> 6;
        int d0 = e & 63;
#pragma unroll
        for (int i = 0; i < 8; i++) {
            int m = m0 + ty * 8 + i;
            int b = m >> 11;               // m / SS
            int s = m & 2047;
            float* dst = g_qkv + ((((which * BB + b) * HH + h) * SS + s) * DD + d0);
#pragma unroll
            for (int j = 0; j < 8; j++) dst[j] = acc[i][j] + bias[n_base + j];
        }
    }
}

// ---------------------------------------------------------------------------
// Fused attention with softmax over the HEAD axis.
// Block = 256 threads: thread (qi, h) with tid = qi*16 + h, TQ=16 queries.
// Streams K/V in chunks of KC=8 keys (all 16 heads) through shared memory.
// For each key: 16 head scores -> softmax across h (width-16 shuffles) ->
// accumulate p * v into per-thread ctx accumulator [64].
// Grid = BB * (SS/16) = 256 blocks.
// ---------------------------------------------------------------------------
#define TQ 16
#define KC 8
#define ATTN_SMEM (2 * KC * 16 * 17 * 16)   // bytes: sk + sv, float4 rows padded to 17

__global__ __launch_bounds__(256) void attn_kernel() {
    extern __shared__ float4 smem[];
    float4* sk = smem;
    float4* sv = smem + KC * 16 * 17;

    int tid = threadIdx.x;
    int h = tid & 15;
    int qi = tid >> 4;
    int blk = blockIdx.x;
    int b = blk >> 7;                 // 128 q-tiles per batch
    int q0 = (blk & 127) * TQ;

    const float4* Qg = (const float4*)(g_qkv + (((0 * BB + b) * HH + h) * SS + (q0 + qi)) * DD);
    const float4* Kg = (const float4*)(g_qkv + ((1 * BB + b) * HH) * SS * DD);
    const float4* Vg = (const float4*)(g_qkv + ((2 * BB + b) * HH) * SS * DD);

    float4 q[16];
#pragma unroll
    for (int i = 0; i < 16; i++) q[i] = Qg[i];

    float4 acc[16];
#pragma unroll
    for (int i = 0; i < 16; i++) acc[i] = make_float4(0.f, 0.f, 0.f, 0.f);

    const float inv_scale = 1.0f / 32.0f;   // 1/sqrt(E)

    for (int kk0 = 0; kk0 < SS; kk0 += KC) {
        // cooperative load: KC*16 rows x 16 float4 per tensor; 8 float4/thread each
#pragma unroll
        for (int r = 0; r < 8; r++) {
            int f = tid + r * 256;
            int i = f & 15;
            int kj = (f >> 4) & (KC - 1);
            int hh = f >> 7;
            int gi = (hh * SS + kk0 + kj) * 16 + i;
            int si = (kj * 16 + hh) * 17 + i;
            sk[si] = Kg[gi];
            sv[si] = Vg[gi];
        }
        __syncthreads();

#pragma unroll
        for (int kj = 0; kj < KC; kj++) {
            const float4* kr = &sk[(kj * 16 + h) * 17];
            float s0 = 0.f, s1 = 0.f, s2 = 0.f, s3 = 0.f;
#pragma unroll
            for (int i = 0; i < 16; i += 4) {
                float4 k0v = kr[i + 0];
                float4 k1v = kr[i + 1];
                float4 k2v = kr[i + 2];
                float4 k3v = kr[i + 3];
                s0 += q[i + 0].x * k0v.x + q[i + 0].y * k0v.y + q[i + 0].z * k0v.z + q[i + 0].w * k0v.w;
                s1 += q[i + 1].x * k1v.x + q[i + 1].y * k1v.y + q[i + 1].z * k1v.z + q[i + 1].w * k1v.w;
                s2 += q[i + 2].x * k2v.x + q[i + 2].y * k2v.y + q[i + 2].z * k2v.z + q[i + 2].w * k2v.w;
                s3 += q[i + 3].x * k3v.x + q[i + 3].y * k3v.y + q[i + 3].z * k3v.z + q[i + 3].w * k3v.w;
            }
            float sc = ((s0 + s1) + (s2 + s3)) * inv_scale;

            // softmax across the 16 heads (lanes h=0..15 within each 16-lane group)
            float mx = sc;
#pragma unroll
            for (int o = 8; o; o >>= 1)
                mx = fmaxf(mx, __shfl_xor_sync(0xffffffffu, mx, o, 16));
            float ev = __expf(sc - mx);
            float sum = ev;
#pragma unroll
            for (int o = 8; o; o >>= 1)
                sum += __shfl_xor_sync(0xffffffffu, sum, o, 16);
            float p = __fdividef(ev, sum);

            const float4* vr = &sv[(kj * 16 + h) * 17];
#pragma unroll
            for (int i = 0; i < 16; i++) {
                float4 v4 = vr[i];
                acc[i].x += p * v4.x;
                acc[i].y += p * v4.y;
                acc[i].z += p * v4.z;
                acc[i].w += p * v4.w;
            }
        }
        __syncthreads();
    }

    // ctx layout [b][s][h*64+d] == [B,S,E] row-major
    float4* dst = (float4*)(g_ctx + ((b * SS + (q0 + qi)) * EE + h * DD));
#pragma unroll
    for (int i = 0; i < 16; i++) dst[i] = acc[i];
}

// ---------------------------------------------------------------------------
// Launch
// ---------------------------------------------------------------------------
extern "C" void kernel_launch(void* const* d_in, const int* in_sizes, int n_in,
                              void* d_out, int out_size) {
    const float* x     = (const float*)d_in[0];   // [2,2048,1024]
    const float* w_qkv = (const float*)d_in[1];   // [3072,1024]
    const float* b_qkv = (const float*)d_in[2];   // [3072]
    const float* w_out = (const float*)d_in[3];   // [1024,1024]
    const float* b_out = (const float*)d_in[4];   // [1024]
    float* out = (float*)d_out;                   // [2,2048,1024]

    cudaFuncSetAttribute(attn_kernel, cudaFuncAttributeMaxDynamicSharedMemorySize,
                         ATTN_SMEM);

    // 1) fused QKV projection, scattered into g_qkv
    {
        dim3 grid(3072 / 128, 4096 / 128);
        sgemm_nt<1, 3072, 1024><<<grid, 256>>>(x, w_qkv, b_qkv, nullptr);
    }
    // 2) fused attention (softmax over heads), writes g_ctx
    attn_kernel<<<BB * (SS / TQ), 256, ATTN_SMEM>>>();
    // 3) output projection
    {
        dim3 grid(1024 / 128, 4096 / 128);
        sgemm_nt<0, 1024, 1024><<<grid, 256>>>(nullptr, w_out, b_out, out);
    }
}

// round 3
// speedup vs baseline: 1.1747x; 1.1747x over previous
#include <cuda_runtime.h>
#include <cstdint>

#define BB 2
#define SS 2048
#define EE 1024
#define HH 16
#define DD 64

__device__ float g_qkv[3 * BB * HH * SS * DD];   // [which][b][h][s][d]
__device__ float g_ctx[BB * SS * EE];            // [b][s][h*64+d]

__device__ __forceinline__ void cp_async16(uint32_t saddr, const void* g) {
    asm volatile("cp.async.cg.shared.global [%0], [%1], 16;\n" :: "r"(saddr), "l"(g));
}
__device__ __forceinline__ void cp_commit() {
    asm volatile("cp.async.commit_group;\n" ::: "memory");
}

// ---------------------------------------------------------------------------
// SGEMM (NT): C[M,N] = A[M,K] @ W[N,K]^T + bias[N]
// Double-buffered smem, register-prefetched LDG, one sync per K-chunk.
// MODE 0: A = g_ctx, row-major out. MODE 1: A = x, scatter into g_qkv.
// ---------------------------------------------------------------------------
template <int MODE, int N, int K>
__global__ __launch_bounds__(256, 2) void sgemm_nt(const float* __restrict__ A,
                                                   const float* __restrict__ W,
                                                   const float* __restrict__ bias,
                                                   float* __restrict__ Cout) {
    __shared__ float As[2][8][132];
    __shared__ float Bs[2][8][132];

    const float* Ap = (MODE == 0) ? (const float*)g_ctx : A;

    int tid = threadIdx.x;
    int m0 = blockIdx.y * 128;
    int n0 = blockIdx.x * 128;
    int tx = tid & 15;
    int ty = tid >> 4;
    int lr = tid >> 1;
    int lk = (tid & 1) * 4;

    float acc[8][8];
#pragma unroll
    for (int i = 0; i < 8; i++)
#pragma unroll
        for (int j = 0; j < 8; j++) acc[i][j] = 0.0f;

    const int NC = K / 8;

    // prologue: chunk 0
    {
        float4 a4 = *(const float4*)(Ap + (m0 + lr) * K + lk);
        float4 b4 = *(const float4*)(W + (n0 + lr) * K + lk);
        As[0][lk + 0][lr] = a4.x; As[0][lk + 1][lr] = a4.y;
        As[0][lk + 2][lr] = a4.z; As[0][lk + 3][lr] = a4.w;
        Bs[0][lk + 0][lr] = b4.x; Bs[0][lk + 1][lr] = b4.y;
        Bs[0][lk + 2][lr] = b4.z; Bs[0][lk + 3][lr] = b4.w;
    }
    __syncthreads();

    for (int c = 0; c < NC; c++) {
        int cur = c & 1;
        float4 a4n, b4n;
        if (c + 1 < NC) {
            int k0 = (c + 1) * 8;
            a4n = *(const float4*)(Ap + (m0 + lr) * K + k0 + lk);
            b4n = *(const float4*)(W + (n0 + lr) * K + k0 + lk);
        }
#pragma unroll
        for (int kk = 0; kk < 8; kk++) {
            float a[8], bb[8];
            *(float4*)&a[0]  = *(const float4*)&As[cur][kk][ty * 8];
            *(float4*)&a[4]  = *(const float4*)&As[cur][kk][ty * 8 + 4];
            *(float4*)&bb[0] = *(const float4*)&Bs[cur][kk][tx * 8];
            *(float4*)&bb[4] = *(const float4*)&Bs[cur][kk][tx * 8 + 4];
#pragma unroll
            for (int i = 0; i < 8; i++)
#pragma unroll
                for (int j = 0; j < 8; j++) acc[i][j] += a[i] * bb[j];
        }
        if (c + 1 < NC) {
            int nxt = (c + 1) & 1;
            As[nxt][lk + 0][lr] = a4n.x; As[nxt][lk + 1][lr] = a4n.y;
            As[nxt][lk + 2][lr] = a4n.z; As[nxt][lk + 3][lr] = a4n.w;
            Bs[nxt][lk + 0][lr] = b4n.x; Bs[nxt][lk + 1][lr] = b4n.y;
            Bs[nxt][lk + 2][lr] = b4n.z; Bs[nxt][lk + 3][lr] = b4n.w;
        }
        __syncthreads();
    }

    if (MODE == 0) {
#pragma unroll
        for (int i = 0; i < 8; i++) {
            int m = m0 + ty * 8 + i;
#pragma unroll
            for (int j = 0; j < 8; j++) {
                int n = n0 + tx * 8 + j;
                Cout[m * N + n] = acc[i][j] + bias[n];
            }
        }
    } else {
        int n_base = n0 + tx * 8;
        int which = n_base >> 10;
        int e = n_base & 1023;
        int h = e >> 6;
        int d0 = e & 63;
#pragma unroll
        for (int i = 0; i < 8; i++) {
            int m = m0 + ty * 8 + i;
            int b = m >> 11;
            int s = m & 2047;
            float* dst = g_qkv + ((((which * BB + b) * HH + h) * SS + s) * DD + d0);
#pragma unroll
            for (int j = 0; j < 8; j++) dst[j] = acc[i][j] + bias[n_base + j];
        }
    }
}

// ---------------------------------------------------------------------------
// Fused attention, softmax over HEAD axis (no max-subtract: |score|<~3).
// TQ=8 queries/block, 128 threads: thread (qi, h), tid = qi*16 + h.
// KC=4 keys per chunk, cp.async double-buffered K/V smem.
// Per chunk: phase A = 4 scores (ILP), phase B = 4 independent softmax
// chains (exp + 4 shuffles each, overlapped), phase C = dense ctx FMA block.
// ---------------------------------------------------------------------------
#define TQ 8
#define KC 4
#define ROWS (KC * 16)            // 64 rows (kj,h) per tensor
#define RP 17                     // padded row stride (float4)
#define BUFQ (ROWS * RP)          // 1088 float4 per tensor per buffer
#define ATTN_SMEM (2 * 2 * BUFQ * 16)   // 69632 bytes

__global__ __launch_bounds__(128, 2) void attn_kernel() {
    extern __shared__ float4 smem[];

    int tid = threadIdx.x;
    int h = tid & 15;
    int qi = tid >> 4;
    int blk = blockIdx.x;
    int b = blk >> 8;                  // 256 q-tiles per batch
    int q0 = (blk & 255) * TQ;

    const float4* Qg = (const float4*)g_qkv + (((0 * BB + b) * HH + h) * SS + (q0 + qi)) * 16;
    const float4* Kg = (const float4*)g_qkv + ((1 * BB + b) * HH) * SS * 16;
    const float4* Vg = (const float4*)g_qkv + ((2 * BB + b) * HH) * SS * 16;

    uint32_t sbase = (uint32_t)__cvta_generic_to_shared(smem);

    float4 q[16];
#pragma unroll
    for (int i = 0; i < 16; i++) q[i] = Qg[i];

    float4 acc[16];
#pragma unroll
    for (int i = 0; i < 16; i++) acc[i] = make_float4(0.f, 0.f, 0.f, 0.f);

    const float inv_scale = 1.0f / 32.0f;
    const int NC = SS / KC;            // 512 chunks

    // per-thread cp.async source/dst mapping (8 float4 per tensor per chunk)
    // f = tid + r*128: i = f&15 (float4 col), row = f>>4 = kj*16 + hh
#pragma unroll 1
    for (int pre = 0; pre < 1; pre++) {
#pragma unroll
        for (int r = 0; r < 8; r++) {
            int f = tid + r * 128;
            int i = f & 15;
            int row = f >> 4;
            int kj = row >> 4;
            int hh = row & 15;
            int gi = (hh * SS + 0 + kj) * 16 + i;
            uint32_t so = (uint32_t)((0 * 2 * BUFQ + row * RP + i) * 16);
            cp_async16(sbase + so, (const void*)(Kg + gi));
            cp_async16(sbase + so + (uint32_t)(BUFQ * 16), (const void*)(Vg + gi));
        }
        cp_commit();
    }

    for (int c = 0; c < NC; c++) {
        if (c + 1 < NC) {
            int kb0 = (c + 1) * KC;
            int bi = (c + 1) & 1;
#pragma unroll
            for (int r = 0; r < 8; r++) {
                int f = tid + r * 128;
                int i = f & 15;
                int row = f >> 4;
                int kj = row >> 4;
                int hh = row & 15;
                int gi = (hh * SS + kb0 + kj) * 16 + i;
                uint32_t so = (uint32_t)((bi * 2 * BUFQ + row * RP + i) * 16);
                cp_async16(sbase + so, (const void*)(Kg + gi));
                cp_async16(sbase + so + (uint32_t)(BUFQ * 16), (const void*)(Vg + gi));
            }
            cp_commit();
            asm volatile("cp.async.wait_group 1;\n" ::: "memory");
        } else {
            asm volatile("cp.async.wait_group 0;\n" ::: "memory");
        }
        __syncthreads();

        const float4* kb = smem + (c & 1) * 2 * BUFQ;
        const float4* vb = kb + BUFQ;

        // Phase A: scores for KC keys (independent -> ILP)
        float sc[KC];
#pragma unroll
        for (int kj = 0; kj < KC; kj++) {
            const float4* kr = &kb[(kj * 16 + h) * RP];
            float s0 = 0.f, s1 = 0.f, s2 = 0.f, s3 = 0.f;
#pragma unroll
            for (int i = 0; i < 16; i += 4) {
                float4 k0v = kr[i + 0];
                float4 k1v = kr[i + 1];
                float4 k2v = kr[i + 2];
                float4 k3v = kr[i + 3];
                s0 += q[i + 0].x * k0v.x + q[i + 0].y * k0v.y + q[i + 0].z * k0v.z + q[i + 0].w * k0v.w;
                s1 += q[i + 1].x * k1v.x + q[i + 1].y * k1v.y + q[i + 1].z * k1v.z + q[i + 1].w * k1v.w;
                s2 += q[i + 2].x * k2v.x + q[i + 2].y * k2v.y + q[i + 2].z * k2v.z + q[i + 2].w * k2v.w;
                s3 += q[i + 3].x * k3v.x + q[i + 3].y * k3v.y + q[i + 3].z * k3v.z + q[i + 3].w * k3v.w;
            }
            sc[kj] = ((s0 + s1) + (s2 + s3)) * inv_scale;
        }

        // Phase B: softmax over heads (width-16 shuffles), chains overlap
        float p[KC];
#pragma unroll
        for (int kj = 0; kj < KC; kj++) p[kj] = __expf(sc[kj]);
#pragma unroll
        for (int kj = 0; kj < KC; kj++) {
            float sum = p[kj];
#pragma unroll
            for (int o = 8; o; o >>= 1)
                sum += __shfl_xor_sync(0xffffffffu, sum, o, 16);
            p[kj] = __fdividef(p[kj], sum);
        }

        // Phase C: ctx accumulation (dense FMA block)
#pragma unroll
        for (int kj = 0; kj < KC; kj++) {
            const float4* vr = &vb[(kj * 16 + h) * RP];
            float pk = p[kj];
#pragma unroll
            for (int i = 0; i < 16; i++) {
                float4 v4 = vr[i];
                acc[i].x += pk * v4.x;
                acc[i].y += pk * v4.y;
                acc[i].z += pk * v4.z;
                acc[i].w += pk * v4.w;
            }
        }
        __syncthreads();
    }

    float4* dst = (float4*)(g_ctx + ((b * SS + (q0 + qi)) * EE + h * DD));
#pragma unroll
    for (int i = 0; i < 16; i++) dst[i] = acc[i];
}

// ---------------------------------------------------------------------------
extern "C" void kernel_launch(void* const* d_in, const int* in_sizes, int n_in,
                              void* d_out, int out_size) {
    const float* x     = (const float*)d_in[0];
    const float* w_qkv = (const float*)d_in[1];
    const float* b_qkv = (const float*)d_in[2];
    const float* w_out = (const float*)d_in[3];
    const float* b_out = (const float*)d_in[4];
    float* out = (float*)d_out;

    cudaFuncSetAttribute(attn_kernel, cudaFuncAttributeMaxDynamicSharedMemorySize,
                         ATTN_SMEM);

    {
        dim3 grid(3072 / 128, 4096 / 128);
        sgemm_nt<1, 3072, 1024><<<grid, 256>>>(x, w_qkv, b_qkv, nullptr);
    }
    attn_kernel<<<BB * (SS / TQ), 128, ATTN_SMEM>>>();
    {
        dim3 grid(1024 / 128, 4096 / 128);
        sgemm_nt<0, 1024, 1024><<<grid, 256>>>(nullptr, w_out, b_out, out);
    }
}

// round 4
// speedup vs baseline: 1.4751x; 1.2558x over previous
#include <cuda_runtime.h>
#include <cstdint>

#define BB 2
#define SS 2048
#define EE 1024
#define HH 16
#define DD 64

__device__ float g_qkv[3 * BB * HH * SS * DD];   // [which][b][h][s][d]
__device__ float g_ctx[BB * SS * EE];            // [b][s][h*64+d]

__device__ __forceinline__ void cp_async16(uint32_t saddr, const void* g) {
    asm volatile("cp.async.cg.shared.global [%0], [%1], 16;\n" :: "r"(saddr), "l"(g));
}
__device__ __forceinline__ void cp_commit() {
    asm volatile("cp.async.commit_group;\n" ::: "memory");
}

// ---------------------------------------------------------------------------
// SGEMM (NT): C[M,N] = A[M,K] @ W[N,K]^T + bias[N]  (unchanged from R3)
// ---------------------------------------------------------------------------
template <int MODE, int N, int K>
__global__ __launch_bounds__(256, 2) void sgemm_nt(const float* __restrict__ A,
                                                   const float* __restrict__ W,
                                                   const float* __restrict__ bias,
                                                   float* __restrict__ Cout) {
    __shared__ float As[2][8][132];
    __shared__ float Bs[2][8][132];

    const float* Ap = (MODE == 0) ? (const float*)g_ctx : A;

    int tid = threadIdx.x;
    int m0 = blockIdx.y * 128;
    int n0 = blockIdx.x * 128;
    int tx = tid & 15;
    int ty = tid >> 4;
    int lr = tid >> 1;
    int lk = (tid & 1) * 4;

    float acc[8][8];
#pragma unroll
    for (int i = 0; i < 8; i++)
#pragma unroll
        for (int j = 0; j < 8; j++) acc[i][j] = 0.0f;

    const int NC = K / 8;

    {
        float4 a4 = *(const float4*)(Ap + (m0 + lr) * K + lk);
        float4 b4 = *(const float4*)(W + (n0 + lr) * K + lk);
        As[0][lk + 0][lr] = a4.x; As[0][lk + 1][lr] = a4.y;
        As[0][lk + 2][lr] = a4.z; As[0][lk + 3][lr] = a4.w;
        Bs[0][lk + 0][lr] = b4.x; Bs[0][lk + 1][lr] = b4.y;
        Bs[0][lk + 2][lr] = b4.z; Bs[0][lk + 3][lr] = b4.w;
    }
    __syncthreads();

    for (int c = 0; c < NC; c++) {
        int cur = c & 1;
        float4 a4n, b4n;
        if (c + 1 < NC) {
            int k0 = (c + 1) * 8;
            a4n = *(const float4*)(Ap + (m0 + lr) * K + k0 + lk);
            b4n = *(const float4*)(W + (n0 + lr) * K + k0 + lk);
        }
#pragma unroll
        for (int kk = 0; kk < 8; kk++) {
            float a[8], bb[8];
            *(float4*)&a[0]  = *(const float4*)&As[cur][kk][ty * 8];
            *(float4*)&a[4]  = *(const float4*)&As[cur][kk][ty * 8 + 4];
            *(float4*)&bb[0] = *(const float4*)&Bs[cur][kk][tx * 8];
            *(float4*)&bb[4] = *(const float4*)&Bs[cur][kk][tx * 8 + 4];
#pragma unroll
            for (int i = 0; i < 8; i++)
#pragma unroll
                for (int j = 0; j < 8; j++) acc[i][j] += a[i] * bb[j];
        }
        if (c + 1 < NC) {
            int nxt = (c + 1) & 1;
            As[nxt][lk + 0][lr] = a4n.x; As[nxt][lk + 1][lr] = a4n.y;
            As[nxt][lk + 2][lr] = a4n.z; As[nxt][lk + 3][lr] = a4n.w;
            Bs[nxt][lk + 0][lr] = b4n.x; Bs[nxt][lk + 1][lr] = b4n.y;
            Bs[nxt][lk + 2][lr] = b4n.z; Bs[nxt][lk + 3][lr] = b4n.w;
        }
        __syncthreads();
    }

    if (MODE == 0) {
#pragma unroll
        for (int i = 0; i < 8; i++) {
            int m = m0 + ty * 8 + i;
#pragma unroll
            for (int j = 0; j < 8; j++) {
                int n = n0 + tx * 8 + j;
                Cout[m * N + n] = acc[i][j] + bias[n];
            }
        }
    } else {
        int n_base = n0 + tx * 8;
        int which = n_base >> 10;
        int e = n_base & 1023;
        int h = e >> 6;
        int d0 = e & 63;
#pragma unroll
        for (int i = 0; i < 8; i++) {
            int m = m0 + ty * 8 + i;
            int b = m >> 11;
            int s = m & 2047;
            float* dst = g_qkv + ((((which * BB + b) * HH + h) * SS + s) * DD + d0);
#pragma unroll
            for (int j = 0; j < 8; j++) dst[j] = acc[i][j] + bias[n_base + j];
        }
    }
}

// ---------------------------------------------------------------------------
// Fused attention, softmax over HEAD axis, non-redundant smem reads.
// 128 threads. Two thread role maps (same bit decomposition of tid):
//   A/C role: h = tid&15, dl = tid>>4  (owns head h, d-slice [dl*8, dl*8+8))
//   reduce:   h = tid&15, qr = tid>>4  (owns query qr, head h)
// Per KC=4 chunk: A: partial scores (K read once) -> sp; reduce: sum over dl,
// exp, width-16 head shuffle-sum, p; C: ctx FMA (V read once, p broadcast).
// ---------------------------------------------------------------------------
#define TQ 8
#define KC 4
#define RP 17                         // float4 row pitch
#define BUFQ (KC * 16 * RP)           // 1088 float4 per tensor per buffer
#define SP_OFF (4 * BUFQ)             // sp: [dl][qi][h] float4 -> 1024 f4
#define P_OFF (SP_OFF + 1024)         // p: [qi][h] float4 -> 128 f4
#define ATTN_SMEM ((P_OFF + 128) * 16)  // 88064 bytes

__global__ __launch_bounds__(128, 2) void attn_kernel() {
    extern __shared__ float4 smem[];

    int tid = threadIdx.x;
    int h = tid & 15;
    int dl = tid >> 4;                // also qr for the reduce role
    int blk = blockIdx.x;
    int b = blk >> 8;
    int q0 = (blk & 255) * TQ;

    const float4* Kg = (const float4*)g_qkv + ((1 * BB + b) * HH) * SS * 16;
    const float4* Vg = (const float4*)g_qkv + ((2 * BB + b) * HH) * SS * 16;

    uint32_t sbase = (uint32_t)__cvta_generic_to_shared(smem);
    float4* sp = smem + SP_OFF;
    float4* pb = smem + P_OFF;

    // q slices in registers: qa/qb[qi] = q[b][h][q0+qi][dl*8 .. dl*8+8)
    float4 qa[TQ], qb[TQ];
#pragma unroll
    for (int qi = 0; qi < TQ; qi++) {
        const float4* Qg = (const float4*)g_qkv + (((0 * BB + b) * HH + h) * SS + (q0 + qi)) * 16 + dl * 2;
        qa[qi] = Qg[0];
        qb[qi] = Qg[1];
    }

    float4 acca[TQ], accb[TQ];
#pragma unroll
    for (int qi = 0; qi < TQ; qi++) {
        acca[qi] = make_float4(0.f, 0.f, 0.f, 0.f);
        accb[qi] = make_float4(0.f, 0.f, 0.f, 0.f);
    }

    const float inv_scale = 1.0f / 32.0f;
    const int NC = SS / KC;

    // prologue: chunk 0 -> buffer 0
#pragma unroll
    for (int r = 0; r < 8; r++) {
        int f = tid + r * 128;
        int i = f & 15;
        int row = f >> 4;             // kj*16 + hh
        int kj = row >> 4;
        int hh = row & 15;
        int gi = (hh * SS + kj) * 16 + i;
        uint32_t so = (uint32_t)((row * RP + i) * 16);
        cp_async16(sbase + so, (const void*)(Kg + gi));
        cp_async16(sbase + so + (uint32_t)(2 * BUFQ * 16), (const void*)(Vg + gi));
    }
    cp_commit();

    for (int c = 0; c < NC; c++) {
        if (c + 1 < NC) {
            int kb0 = (c + 1) * KC;
            int bi = (c + 1) & 1;
#pragma unroll
            for (int r = 0; r < 8; r++) {
                int f = tid + r * 128;
                int i = f & 15;
                int row = f >> 4;
                int kj = row >> 4;
                int hh = row & 15;
                int gi = (hh * SS + kb0 + kj) * 16 + i;
                uint32_t so = (uint32_t)((bi * BUFQ + row * RP + i) * 16);
                cp_async16(sbase + so, (const void*)(Kg + gi));
                cp_async16(sbase + so + (uint32_t)(2 * BUFQ * 16), (const void*)(Vg + gi));
            }
            cp_commit();
            asm volatile("cp.async.wait_group 1;\n" ::: "memory");
        } else {
            asm volatile("cp.async.wait_group 0;\n" ::: "memory");
        }
        __syncthreads();                               // bar1: buffers ready

        const float4* kbuf = smem + (c & 1) * BUFQ;
        const float4* vbuf = kbuf + 2 * BUFQ;

        // ---- Phase A: partial scores; each K slice read once ----
        float s[TQ][KC];
#pragma unroll
        for (int kj = 0; kj < KC; kj++) {
            const float4* kr = &kbuf[(kj * 16 + h) * RP + dl * 2];
            float4 kA = kr[0];
            float4 kB = kr[1];
#pragma unroll
            for (int qi = 0; qi < TQ; qi++) {
                float d = qa[qi].x * kA.x + qa[qi].y * kA.y + qa[qi].z * kA.z + qa[qi].w * kA.w
                        + qb[qi].x * kB.x + qb[qi].y * kB.y + qb[qi].z * kB.z + qb[qi].w * kB.w;
                s[qi][kj] = d;
            }
        }
#pragma unroll
        for (int qi = 0; qi < TQ; qi++)
            sp[dl * 128 + qi * 16 + h] = make_float4(s[qi][0], s[qi][1], s[qi][2], s[qi][3]);
        __syncthreads();                               // bar2: sp ready

        // ---- Reduce + softmax over heads (thread = (qr=dl, h)) ----
        {
            int qr = dl;
            float4 t = sp[qr * 16 + h];
#pragma unroll
            for (int d2 = 1; d2 < 8; d2++) {
                float4 u = sp[d2 * 128 + qr * 16 + h];
                t.x += u.x; t.y += u.y; t.z += u.z; t.w += u.w;
            }
            float4 e;
            e.x = __expf(t.x * inv_scale);
            e.y = __expf(t.y * inv_scale);
            e.z = __expf(t.z * inv_scale);
            e.w = __expf(t.w * inv_scale);
            float4 sum = e;
#pragma unroll
            for (int o = 8; o; o >>= 1) {
                sum.x += __shfl_xor_sync(0xffffffffu, sum.x, o, 16);
                sum.y += __shfl_xor_sync(0xffffffffu, sum.y, o, 16);
                sum.z += __shfl_xor_sync(0xffffffffu, sum.z, o, 16);
                sum.w += __shfl_xor_sync(0xffffffffu, sum.w, o, 16);
            }
            float4 p4;
            p4.x = __fdividef(e.x, sum.x);
            p4.y = __fdividef(e.y, sum.y);
            p4.z = __fdividef(e.z, sum.z);
            p4.w = __fdividef(e.w, sum.w);
            pb[qr * 16 + h] = p4;
        }
        __syncthreads();                               // bar3: p ready

        // ---- Phase C: ctx accumulation; each V slice read once ----
        float4 pq[TQ];
#pragma unroll
        for (int qi = 0; qi < TQ; qi++) pq[qi] = pb[qi * 16 + h];

#pragma unroll
        for (int kj = 0; kj < KC; kj++) {
            const float4* vr = &vbuf[(kj * 16 + h) * RP + dl * 2];
            float4 vA = vr[0];
            float4 vB = vr[1];
#pragma unroll
            for (int qi = 0; qi < TQ; qi++) {
                float pk = (kj == 0) ? pq[qi].x : (kj == 1) ? pq[qi].y : (kj == 2) ? pq[qi].z : pq[qi].w;
                acca[qi].x += pk * vA.x; acca[qi].y += pk * vA.y;
                acca[qi].z += pk * vA.z; acca[qi].w += pk * vA.w;
                accb[qi].x += pk * vB.x; accb[qi].y += pk * vB.y;
                accb[qi].z += pk * vB.z; accb[qi].w += pk * vB.w;
            }
        }
        __syncthreads();                               // bar4: protect reuse
    }

    // ctx[b][q0+qi][h*64 + dl*8 .. +8]
#pragma unroll
    for (int qi = 0; qi < TQ; qi++) {
        float4* dst = (float4*)g_ctx + (b * SS + q0 + qi) * 256 + h * 16 + dl * 2;
        dst[0] = acca[qi];
        dst[1] = accb[qi];
    }
}

// ---------------------------------------------------------------------------
extern "C" void kernel_launch(void* const* d_in, const int* in_sizes, int n_in,
                              void* d_out, int out_size) {
    const float* x     = (const float*)d_in[0];
    const float* w_qkv = (const float*)d_in[1];
    const float* b_qkv = (const float*)d_in[2];
    const float* w_out = (const float*)d_in[3];
    const float* b_out = (const float*)d_in[4];
    float* out = (float*)d_out;

    cudaFuncSetAttribute(attn_kernel, cudaFuncAttributeMaxDynamicSharedMemorySize,
                         ATTN_SMEM);

    {
        dim3 grid(3072 / 128, 4096 / 128);
        sgemm_nt<1, 3072, 1024><<<grid, 256>>>(x, w_qkv, b_qkv, nullptr);
    }
    attn_kernel<<<BB * (SS / TQ), 128, ATTN_SMEM>>>();
    {
        dim3 grid(1024 / 128, 4096 / 128);
        sgemm_nt<0, 1024, 1024><<<grid, 256>>>(nullptr, w_out, b_out, out);
    }
}

// round 6
// speedup vs baseline: 1.8690x; 1.2671x over previous
#include <cuda_runtime.h>
#include <cuda_bf16.h>
#include <cstdint>

#define BB 2
#define SS 2048
#define EE 1024
#define HH 16
#define DD 64

__device__ float g_qkv[3 * BB * HH * SS * DD];   // [which][b][h][s][d]
__device__ float g_ctx[BB * SS * EE];            // [b][s][h*64+d]

// bf16 hi/lo split buffers
__device__ __nv_bfloat16 g_a_hi[4096 * 1024];    // x, later ctx
__device__ __nv_bfloat16 g_a_lo[4096 * 1024];
__device__ __nv_bfloat16 g_wq_hi[3072 * 1024];
__device__ __nv_bfloat16 g_wq_lo[3072 * 1024];
__device__ __nv_bfloat16 g_wo_hi[1024 * 1024];
__device__ __nv_bfloat16 g_wo_lo[1024 * 1024];

// ===========================================================================
// helpers
// ===========================================================================
__device__ __forceinline__ uint32_t smem_u32(const void* p) {
    uint32_t a;
    asm("{ .reg .u64 t; cvta.to.shared.u64 t, %1; cvt.u32.u64 %0, t; }"
        : "=r"(a) : "l"(p));
    return a;
}
__device__ __forceinline__ void cp_async16(uint32_t saddr, const void* g) {
    asm volatile("cp.async.cg.shared.global [%0], [%1], 16;\n" :: "r"(saddr), "l"(g));
}
__device__ __forceinline__ void cp_commit() {
    asm volatile("cp.async.commit_group;\n" ::: "memory");
}
__device__ __forceinline__ void ldsm4(uint32_t& r0, uint32_t& r1, uint32_t& r2,
                                      uint32_t& r3, uint32_t a) {
    asm volatile("ldmatrix.sync.aligned.m8n8.x4.shared.b16 {%0,%1,%2,%3}, [%4];"
                 : "=r"(r0), "=r"(r1), "=r"(r2), "=r"(r3) : "r"(a));
}
__device__ __forceinline__ void mma_bf16(float* c, const uint32_t* a, uint32_t b0,
                                         uint32_t b1) {
    asm volatile(
        "mma.sync.aligned.m16n8k16.row.col.f32.bf16.bf16.f32 "
        "{%0,%1,%2,%3},{%4,%5,%6,%7},{%8,%9},{%0,%1,%2,%3};"
        : "+f"(c[0]), "+f"(c[1]), "+f"(c[2]), "+f"(c[3])
        : "r"(a[0]), "r"(a[1]), "r"(a[2]), "r"(a[3]), "r"(b0), "r"(b1));
}
__device__ __forceinline__ void split4(float4 v, uint32_t& h01, uint32_t& h23,
                                       uint32_t& l01, uint32_t& l23) {
    asm("cvt.rn.bf16x2.f32 %0, %1, %2;" : "=r"(h01) : "f"(v.y), "f"(v.x));
    asm("cvt.rn.bf16x2.f32 %0, %1, %2;" : "=r"(h23) : "f"(v.w), "f"(v.z));
    float q0 = v.x - __uint_as_float(h01 << 16);
    float q1 = v.y - __uint_as_float(h01 & 0xffff0000u);
    float q2 = v.z - __uint_as_float(h23 << 16);
    float q3 = v.w - __uint_as_float(h23 & 0xffff0000u);
    asm("cvt.rn.bf16x2.f32 %0, %1, %2;" : "=r"(l01) : "f"(q1), "f"(q0));
    asm("cvt.rn.bf16x2.f32 %0, %1, %2;" : "=r"(l23) : "f"(q3), "f"(q2));
}

// ===========================================================================
// fp32 -> bf16 hi/lo split (one pass per tensor)
// DST: 0 = g_a (x or ctx), 1 = g_wq, 2 = g_wo
// ===========================================================================
template <int DST>
__global__ __launch_bounds__(256) void cvt_split(const float4* __restrict__ src) {
    int i = blockIdx.x * 256 + threadIdx.x;
    float4 v = src[i];
    uint32_t h01, h23, l01, l23;
    split4(v, h01, h23, l01, l23);
    uint2* hp = (uint2*)(DST == 0 ? g_a_hi : DST == 1 ? g_wq_hi : g_wo_hi);
    uint2* lp = (uint2*)(DST == 0 ? g_a_lo : DST == 1 ? g_wq_lo : g_wo_lo);
    hp[i] = make_uint2(h01, h23);
    lp[i] = make_uint2(l01, l23);
}

// ===========================================================================
// HMMA bf16-split GEMM: C[M,N] = A[M,K] @ W[N,K]^T + bias
// 128x128 CTA tile, BK=32, 256 thr (8 warps, 4x2), warp tile 32x64.
// smem: 4 tiles (Ah, Al, Wh, Wl) of 128 rows x 80B, double buffered.
// MODE 0: A = g_a(ctx), W = g_wo, row-major out.  MODE 1: A = g_a(x),
// W = g_wq, scatter into g_qkv.
// ===========================================================================
#define TILE_B 10240
#define BUF_B (4 * TILE_B)
#define GEMM_SMEM (2 * BUF_B)

template <int MODE, int N, int K>
__global__ __launch_bounds__(256, 2) void tgemm(const float* __restrict__ bias,
                                                float* __restrict__ Cout) {
    extern __shared__ char dsm[];
    uint32_t sbase = smem_u32(dsm);

    const __nv_bfloat16* Ah = g_a_hi;
    const __nv_bfloat16* Al = g_a_lo;
    const __nv_bfloat16* Wh = (MODE == 1) ? g_wq_hi : g_wo_hi;
    const __nv_bfloat16* Wl = (MODE == 1) ? g_wq_lo : g_wo_lo;

    int tid = threadIdx.x, lane = tid & 31, wid = tid >> 5;
    int wm = wid & 3, wn = wid >> 2;
    int m0 = blockIdx.y * 128, n0 = blockIdx.x * 128;

    float acc[2][8][4];
#pragma unroll
    for (int i = 0; i < 2; i++)
#pragma unroll
        for (int j = 0; j < 8; j++)
#pragma unroll
            for (int q = 0; q < 4; q++) acc[i][j][q] = 0.f;

    const int NC = K / 32;
    const int lrow = tid >> 2;       // 0..63
    const int seg = tid & 3;

    // issue chunk c into buffer (c&1)
    auto issue = [&](int c) {
        int buf = c & 1;
        uint32_t sb = sbase + buf * BUF_B;
        size_t gcol = (size_t)c * 32 + seg * 8;
#pragma unroll
        for (int rr = 0; rr < 2; rr++) {
            int row = lrow + rr * 64;
            uint32_t soff = (uint32_t)(row * 80 + seg * 16);
            cp_async16(sb + 0 * TILE_B + soff, Ah + (size_t)(m0 + row) * K + gcol);
            cp_async16(sb + 1 * TILE_B + soff, Al + (size_t)(m0 + row) * K + gcol);
            cp_async16(sb + 2 * TILE_B + soff, Wh + (size_t)(n0 + row) * K + gcol);
            cp_async16(sb + 3 * TILE_B + soff, Wl + (size_t)(n0 + row) * K + gcol);
        }
        cp_commit();
    };

    issue(0);

    for (int c = 0; c < NC; c++) {
        if (c + 1 < NC) {
            issue(c + 1);
            asm volatile("cp.async.wait_group 1;\n" ::: "memory");
        } else {
            asm volatile("cp.async.wait_group 0;\n" ::: "memory");
        }
        __syncthreads();

        uint32_t sb = sbase + (c & 1) * BUF_B;
        // ldmatrix base addresses for this thread
        uint32_t a_addr = sb + (uint32_t)((wm * 32 + (lane & 15)) * 80 + (lane >> 4) * 16);
        uint32_t b_addr = sb + 2 * TILE_B +
                          (uint32_t)((wn * 64 + (lane >> 4) * 8 + (lane & 7)) * 80 +
                                     ((lane >> 3) & 1) * 16);

#pragma unroll
        for (int ks = 0; ks < 2; ks++) {
            uint32_t ah[2][4], al[2][4];
#pragma unroll
            for (int mb = 0; mb < 2; mb++) {
                uint32_t ao = a_addr + ks * 32 + mb * (16 * 80);
                ldsm4(ah[mb][0], ah[mb][1], ah[mb][2], ah[mb][3], ao);
                ldsm4(al[mb][0], al[mb][1], al[mb][2], al[mb][3], ao + TILE_B);
            }
#pragma unroll
            for (int np = 0; np < 4; np++) {
                uint32_t bo = b_addr + ks * 32 + np * (16 * 80);
                uint32_t h0, h1, h2, h3, l0, l1, l2, l3;
                ldsm4(h0, h1, h2, h3, bo);
                ldsm4(l0, l1, l2, l3, bo + TILE_B);
#pragma unroll
                for (int mb = 0; mb < 2; mb++) {
                    mma_bf16(acc[mb][2 * np],     ah[mb], h0, h1);
                    mma_bf16(acc[mb][2 * np],     al[mb], h0, h1);
                    mma_bf16(acc[mb][2 * np],     ah[mb], l0, l1);
                    mma_bf16(acc[mb][2 * np + 1], ah[mb], h2, h3);
                    mma_bf16(acc[mb][2 * np + 1], al[mb], h2, h3);
                    mma_bf16(acc[mb][2 * np + 1], ah[mb], l2, l3);
                }
            }
        }
        __syncthreads();
    }

    // epilogue
    int lr = lane >> 2, lc = lane & 3;
#pragma unroll
    for (int mb = 0; mb < 2; mb++) {
#pragma unroll
        for (int nb = 0; nb < 8; nb++) {
            int n = n0 + wn * 64 + nb * 8 + lc * 2;
            float2 bv = *(const float2*)(bias + n);
            int m_lo = m0 + wm * 32 + mb * 16 + lr;
            float* a4 = acc[mb][nb];
            if (MODE == 0) {
                *(float2*)(Cout + (size_t)m_lo * N + n) =
                    make_float2(a4[0] + bv.x, a4[1] + bv.y);
                *(float2*)(Cout + (size_t)(m_lo + 8) * N + n) =
                    make_float2(a4[2] + bv.x, a4[3] + bv.y);
            } else {
                int which = n >> 10;
                int h = (n & 1023) >> 6;
                int d = n & 63;
#pragma unroll
                for (int half = 0; half < 2; half++) {
                    int m = m_lo + half * 8;
                    int b = m >> 11;
                    int s = m & 2047;
                    float* dst = g_qkv +
                        ((((size_t)which * BB + b) * HH + h) * SS + s) * DD + d;
                    *(float2*)dst = make_float2(a4[2 * half] + bv.x,
                                                a4[2 * half + 1] + bv.y);
                }
            }
        }
    }
}

// ===========================================================================
// Fused attention (unchanged, passing since R4): softmax over HEAD axis.
// ===========================================================================
#define TQ 8
#define KC 4
#define RP 17
#define BUFQ (KC * 16 * RP)
#define SP_OFF (4 * BUFQ)
#define P_OFF (SP_OFF + 1024)
#define ATTN_SMEM ((P_OFF + 128) * 16)

__global__ __launch_bounds__(128, 2) void attn_kernel() {
    extern __shared__ float4 smem[];

    int tid = threadIdx.x;
    int h = tid & 15;
    int dl = tid >> 4;
    int blk = blockIdx.x;
    int b = blk >> 8;
    int q0 = (blk & 255) * TQ;

    const float4* Kg = (const float4*)g_qkv + ((1 * BB + b) * HH) * SS * 16;
    const float4* Vg = (const float4*)g_qkv + ((2 * BB + b) * HH) * SS * 16;

    uint32_t sbase = smem_u32(smem);
    float4* sp = smem + SP_OFF;
    float4* pb = smem + P_OFF;

    float4 qa[TQ], qb[TQ];
#pragma unroll
    for (int qi = 0; qi < TQ; qi++) {
        const float4* Qg = (const float4*)g_qkv + (((0 * BB + b) * HH + h) * SS + (q0 + qi)) * 16 + dl * 2;
        qa[qi] = Qg[0];
        qb[qi] = Qg[1];
    }

    float4 acca[TQ], accb[TQ];
#pragma unroll
    for (int qi = 0; qi < TQ; qi++) {
        acca[qi] = make_float4(0.f, 0.f, 0.f, 0.f);
        accb[qi] = make_float4(0.f, 0.f, 0.f, 0.f);
    }

    const float inv_scale = 1.0f / 32.0f;
    const int NC = SS / KC;

#pragma unroll
    for (int rr = 0; rr < 8; rr++) {
        int f = tid + rr * 128;
        int i = f & 15;
        int row = f >> 4;
        int kj = row >> 4;
        int hh = row & 15;
        int gi = (hh * SS + kj) * 16 + i;
        uint32_t so = (uint32_t)((row * RP + i) * 16);
        cp_async16(sbase + so, (const void*)(Kg + gi));
        cp_async16(sbase + so + (uint32_t)(2 * BUFQ * 16), (const void*)(Vg + gi));
    }
    cp_commit();

    for (int c = 0; c < NC; c++) {
        if (c + 1 < NC) {
            int kb0 = (c + 1) * KC;
            int bi = (c + 1) & 1;
#pragma unroll
            for (int rr = 0; rr < 8; rr++) {
                int f = tid + rr * 128;
                int i = f & 15;
                int row = f >> 4;
                int kj = row >> 4;
                int hh = row & 15;
                int gi = (hh * SS + kb0 + kj) * 16 + i;
                uint32_t so = (uint32_t)((bi * BUFQ + row * RP + i) * 16);
                cp_async16(sbase + so, (const void*)(Kg + gi));
                cp_async16(sbase + so + (uint32_t)(2 * BUFQ * 16), (const void*)(Vg + gi));
            }
            cp_commit();
            asm volatile("cp.async.wait_group 1;\n" ::: "memory");
        } else {
            asm volatile("cp.async.wait_group 0;\n" ::: "memory");
        }
        __syncthreads();

        const float4* kbuf = smem + (c & 1) * BUFQ;
        const float4* vbuf = kbuf + 2 * BUFQ;

        float s[TQ][KC];
#pragma unroll
        for (int kj = 0; kj < KC; kj++) {
            const float4* kr = &kbuf[(kj * 16 + h) * RP + dl * 2];
            float4 kA = kr[0];
            float4 kB = kr[1];
#pragma unroll
            for (int qi = 0; qi < TQ; qi++) {
                s[qi][kj] = qa[qi].x * kA.x + qa[qi].y * kA.y + qa[qi].z * kA.z + qa[qi].w * kA.w
                          + qb[qi].x * kB.x + qb[qi].y * kB.y + qb[qi].z * kB.z + qb[qi].w * kB.w;
            }
        }
#pragma unroll
        for (int qi = 0; qi < TQ; qi++)
            sp[dl * 128 + qi * 16 + h] = make_float4(s[qi][0], s[qi][1], s[qi][2], s[qi][3]);
        __syncthreads();

        {
            int qr = dl;
            float4 t = sp[qr * 16 + h];
#pragma unroll
            for (int d2 = 1; d2 < 8; d2++) {
                float4 u = sp[d2 * 128 + qr * 16 + h];
                t.x += u.x; t.y += u.y; t.z += u.z; t.w += u.w;
            }
            float4 e;
            e.x = __expf(t.x * inv_scale);
            e.y = __expf(t.y * inv_scale);
            e.z = __expf(t.z * inv_scale);
            e.w = __expf(t.w * inv_scale);
            float4 sum = e;
#pragma unroll
            for (int o = 8; o; o >>= 1) {
                sum.x += __shfl_xor_sync(0xffffffffu, sum.x, o, 16);
                sum.y += __shfl_xor_sync(0xffffffffu, sum.y, o, 16);
                sum.z += __shfl_xor_sync(0xffffffffu, sum.z, o, 16);
                sum.w += __shfl_xor_sync(0xffffffffu, sum.w, o, 16);
            }
            float4 p4;
            p4.x = __fdividef(e.x, sum.x);
            p4.y = __fdividef(e.y, sum.y);
            p4.z = __fdividef(e.z, sum.z);
            p4.w = __fdividef(e.w, sum.w);
            pb[qr * 16 + h] = p4;
        }
        __syncthreads();

        float4 pq[TQ];
#pragma unroll
        for (int qi = 0; qi < TQ; qi++) pq[qi] = pb[qi * 16 + h];

#pragma unroll
        for (int kj = 0; kj < KC; kj++) {
            const float4* vr = &vbuf[(kj * 16 + h) * RP + dl * 2];
            float4 vA = vr[0];
            float4 vB = vr[1];
#pragma unroll
            for (int qi = 0; qi < TQ; qi++) {
                float pk = (kj == 0) ? pq[qi].x : (kj == 1) ? pq[qi].y : (kj == 2) ? pq[qi].z : pq[qi].w;
                acca[qi].x += pk * vA.x; acca[qi].y += pk * vA.y;
                acca[qi].z += pk * vA.z; acca[qi].w += pk * vA.w;
                accb[qi].x += pk * vB.x; accb[qi].y += pk * vB.y;
                accb[qi].z += pk * vB.z; accb[qi].w += pk * vB.w;
            }
        }
        __syncthreads();
    }

#pragma unroll
    for (int qi = 0; qi < TQ; qi++) {
        float4* dst = (float4*)g_ctx + (b * SS + q0 + qi) * 256 + h * 16 + dl * 2;
        dst[0] = acca[qi];
        dst[1] = accb[qi];
    }
}

// ===========================================================================
extern "C" void kernel_launch(void* const* d_in, const int* in_sizes, int n_in,
                              void* d_out, int out_size) {
    const float* x     = (const float*)d_in[0];
    const float* w_qkv = (const float*)d_in[1];
    const float* b_qkv = (const float*)d_in[2];
    const float* w_out = (const float*)d_in[3];
    const float* b_out = (const float*)d_in[4];
    float* out = (float*)d_out;

    cudaFuncSetAttribute(tgemm<1, 3072, 1024>, cudaFuncAttributeMaxDynamicSharedMemorySize, GEMM_SMEM);
    cudaFuncSetAttribute(tgemm<0, 1024, 1024>, cudaFuncAttributeMaxDynamicSharedMemorySize, GEMM_SMEM);
    cudaFuncSetAttribute(attn_kernel, cudaFuncAttributeMaxDynamicSharedMemorySize, ATTN_SMEM);

    // split inputs to bf16 hi/lo
    cvt_split<0><<<(4096 * 1024 / 4) / 256, 256>>>((const float4*)x);
    cvt_split<1><<<(3072 * 1024 / 4) / 256, 256>>>((const float4*)w_qkv);
    cvt_split<2><<<(1024 * 1024 / 4) / 256, 256>>>((const float4*)w_out);

    // QKV projection (HMMA), scatter into g_qkv
    {
        dim3 grid(3072 / 128, 4096 / 128);
        tgemm<1, 3072, 1024><<<grid, 256, GEMM_SMEM>>>(b_qkv, nullptr);
    }
    // attention
    attn_kernel<<<BB * (SS / TQ), 128, ATTN_SMEM>>>();
    // split ctx, then output projection
    {
        float* ctxp = nullptr;
        cudaGetSymbolAddress((void**)&ctxp, g_ctx);
        cvt_split<0><<<(4096 * 1024 / 4) / 256, 256>>>((const float4*)ctxp);
        dim3 grid(1024 / 128, 4096 / 128);
        tgemm<0, 1024, 1024><<<grid, 256, GEMM_SMEM>>>(b_out, out);
    }
}